// round 13
// baseline (speedup 1.0000x reference)
#include <cuda_runtime.h>
#include <cuda_bf16.h>

#define BB 64
#define TT 1024
#define DD 64
#define HH 4
#define NRANK 8
#define RPC 128
#define STRIDE 68
#define NEGF (-4294967296.0f)

// ---------------- smem layout (floats) ----------------
#define OFF_KS   0          // key tile 128x68 = 8704 (FFN overlay later)
#define OFF_P4   8704       // 512 (p per row, 4 heads)
#define OFF_ACC  9216       // 1024 (reduce scratch; later s_sm[256]+part[256])
#define OFF_U    10240      // 256  (u planar [h][d])
#define OFF_Q0   10496      // 64
#define OFF_QH   10560      // 64
#define OFF_WRED 10624      // 32
#define OFF_MH   10656      // 4
#define OFF_MS   10660      // 32
#define OFF_LS   10692      // 32
#define OFF_FS   10724      // 32
#define OFF_SC   10756      // 4
#define OFF_QM   10760      // 4
#define SM_FLOATS 10764
#define SM_BYTES (SM_FLOATS * 4)

// FFN overlay inside dead key tile (float offsets from OFF_KS)
#define FO_FW1   0          // 2048: fw1 col-slice [64 j][32 m]
#define FO_FW2   2048       // 2048: fw2 row-slice [32 m][64 j]
#define FO_FB1   4096       // 32
#define FO_FB2   4128       // 64
#define FO_RES   4192       // 64
#define FO_HID   4256       // 32

#define CP_ASYNC16(dst_u32, src) \
    asm volatile("cp.async.cg.shared.global [%0], [%1], 16;" :: "r"(dst_u32), "l"(src) : "memory")
#define CP_COMMIT() asm volatile("cp.async.commit_group;" ::: "memory")
#define CP_WAIT_GROUP(n) asm volatile("cp.async.wait_group %0;" :: "n"(n) : "memory")

// cross-CTA exchange (ordered by cluster barriers within one replay)
__device__ float g_u[BB * 256];                  // [b][h*64+d] planar
__device__ float g_pacc[BB * NRANK * HH * DD];   // [b][s][h*64+d]
__device__ float g_pm[BB * NRANK * HH];          // [b][s*4+h]
__device__ float g_pl[BB * NRANK * HH];

__global__ __launch_bounds__(256, 4) __cluster_dims__(NRANK, 1, 1)
void fused_transformer_kernel(
    const float* __restrict__ queries, const float* __restrict__ keys,
    const int* __restrict__ query_mask, const int* __restrict__ key_mask,
    const float* __restrict__ W_Q, const float* __restrict__ W_K,
    const float* __restrict__ W_V,
    const float* __restrict__ fw1, const float* __restrict__ fw2,
    const float* __restrict__ fb1, const float* __restrict__ fb2,
    float* __restrict__ out)
{
    extern __shared__ float sm[];
    const unsigned sbase = (unsigned)__cvta_generic_to_shared(sm);

    float*  ks   = sm + OFF_KS;
    float4* p4   = (float4*)(sm + OFF_P4);
    float*  accf = sm + OFF_ACC;
    float*  u_s  = sm + OFF_U;
    float*  q0   = sm + OFF_Q0;
    float*  Qh   = sm + OFF_QH;
    float*  wred = sm + OFF_WRED;
    float*  mh   = sm + OFF_MH;
    float*  m_s  = sm + OFF_MS;
    float*  l_s  = sm + OFF_LS;
    float*  f_s  = sm + OFF_FS;
    float*  sc_s = sm + OFF_SC;

    const int r    = blockIdx.x;          // cluster rank 0..7 = split
    const int b    = blockIdx.y;
    const int t    = threadIdx.x;
    const int k0   = r * RPC;
    const int lane = t & 31;
    const int wid  = t >> 5;

    if (r == 0 && t < 64) out[b * 64 + t] = 0.f;   // ordered before adds via barrier #2

    // ---- key tile DMA: 128 rows x 16 f4 = 2048 f4, 8 per thread ----
    {
        const float4* kg = (const float4*)(keys + ((size_t)b * TT + k0) * DD);
        #pragma unroll
        for (int i = 0; i < 8; i++) {
            int idx = t + i * 256;
            int row = idx >> 4, c = idx & 15;
            CP_ASYNC16(sbase + (row * STRIDE + c * 4) * 4, kg + idx);
        }
        CP_COMMIT();
    }
    const int row = t & 127;       // score row
    const int hp  = t >> 7;        // head-pair 0/1
    const int kmv = key_mask[b * TT + k0 + row];
    if (t < 16) ((float4*)q0)[t] = ((const float4*)(queries + (size_t)b * TT * DD))[t];
    if (t == 64) sm[OFF_QM] = (float)query_mask[b * TT];

    // ---- rank 0: compute u (overlaps every rank's key DMA) ----
    if (r == 0) {
        __syncthreads();   // q0 visible
        {
            int j = t & 63, q = t >> 6;
            float a = 0.f;
            #pragma unroll
            for (int i = q * 16; i < q * 16 + 16; i++) a += q0[i] * W_Q[i * 64 + j];
            accf[t] = a;
        }
        __syncthreads();
        if (t < 64) Qh[t] = accf[t] + accf[64 + t] + accf[128 + t] + accf[192 + t];
        __syncthreads();
        {
            int d = t & 63, h = t >> 6;
            const float4* wr  = (const float4*)(W_K + d * 64 + h * 16);
            const float4* qh4 = (const float4*)(Qh + h * 16);
            float s = 0.f;
            #pragma unroll
            for (int c = 0; c < 4; c++) {
                float4 w = wr[c]; float4 q = qh4[c];
                s += w.x * q.x + w.y * q.y + w.z * q.z + w.w * q.w;
            }
            g_u[b * 256 + h * 64 + d] = s * 0.25f;   // planar publish
        }
        __threadfence();
    }

    // ---- barrier #1: u published (hidden under key DMA) ----
    asm volatile("barrier.cluster.arrive.aligned;" ::: "memory");
    asm volatile("barrier.cluster.wait.aligned;"   ::: "memory");

    if (t < 64) ((float4*)u_s)[t] = ((const float4*)(g_u + b * 256))[t];
    CP_WAIT_GROUP(0);
    __syncthreads();

    // ---- scores: thread = (row, 2 heads) ----
    float s0, s1;
    {
        const float4* krow = (const float4*)&ks[row * STRIDE];
        const float4* uh0 = (const float4*)(u_s + (2 * hp) * 64);
        const float4* uh1 = uh0 + 16;
        float a0 = 0.f, a1 = 0.f;
        #pragma unroll
        for (int c = 0; c < 16; c++) {
            float4 kv = krow[c];
            float4 ua = uh0[c], ub = uh1[c];
            a0 += kv.x * ua.x + kv.y * ua.y + kv.z * ua.z + kv.w * ua.w;
            a1 += kv.x * ub.x + kv.y * ub.y + kv.z * ub.z + kv.w * ub.w;
        }
        bool masked = (kmv != 1) || ((k0 + row) == 0);
        s0 = masked ? NEGF : a0;
        s1 = masked ? NEGF : a1;
    }
    // warp max (warps 0-3: heads 0,1 ; warps 4-7: heads 2,3)
    {
        float m0 = s0, m1 = s1;
        #pragma unroll
        for (int o = 16; o; o >>= 1) {
            m0 = fmaxf(m0, __shfl_xor_sync(0xffffffffu, m0, o));
            m1 = fmaxf(m1, __shfl_xor_sync(0xffffffffu, m1, o));
        }
        if (lane == 0) { wred[wid * 2] = m0; wred[wid * 2 + 1] = m1; }
    }
    __syncthreads();
    if (t < 4) {
        int base = (t < 2) ? 0 : 8;
        int col = (t < 2) ? t : (t - 2);
        float m = wred[base + col];
        #pragma unroll
        for (int w = 1; w < 4; w++) m = fmaxf(m, wred[base + w * 2 + col]);
        mh[t] = m;
    }
    __syncthreads();

    // p = exp(s - m); warp sums
    {
        float p0 = __expf(s0 - mh[2 * hp]);
        float p1 = __expf(s1 - mh[2 * hp + 1]);
        ((float2*)&p4[row])[hp] = make_float2(p0, p1);
        float l0 = p0, l1 = p1;
        #pragma unroll
        for (int o = 16; o; o >>= 1) {
            l0 += __shfl_xor_sync(0xffffffffu, l0, o);
            l1 += __shfl_xor_sync(0xffffffffu, l1, o);
        }
        if (lane == 0) { wred[wid * 2] = l0; wred[wid * 2 + 1] = l1; }
    }
    __syncthreads();
    if (t < 4) {
        int base = (t < 2) ? 0 : 8;
        int col = (t < 2) ? t : (t - 2);
        float l = wred[base + col];
        #pragma unroll
        for (int w = 1; w < 4; w++) l += wred[base + w * 2 + col];
        g_pm[b * (NRANK * HH) + r * HH + t] = mh[t];
        g_pl[b * (NRANK * HH) + r * HH + t] = l;
    }

    // ---- weighted key sum: thread (d, quarter) over 32 rows ----
    {
        int d = t & 63, q = t >> 6;
        float ax = 0.f, ay = 0.f, az = 0.f, aw = 0.f;
        const int kb = q * 32;
        #pragma unroll 4
        for (int kk = 0; kk < 32; kk++) {
            float kv = ks[(kb + kk) * STRIDE + d];
            float4 p = p4[kb + kk];
            ax += p.x * kv; ay += p.y * kv; az += p.z * kv; aw += p.w * kv;
        }
        ((float4*)accf)[t] = make_float4(ax, ay, az, aw);
    }
    __syncthreads();
    if (t < 64) {
        float4* am = (float4*)accf;
        float4 a = am[t], c = am[64 + t], d4 = am[128 + t], e = am[192 + t];
        float* gp = g_pacc + (b * NRANK + r) * 256;
        gp[0 * 64 + t] = a.x + c.x + d4.x + e.x;
        gp[1 * 64 + t] = a.y + c.y + d4.y + e.y;
        gp[2 * 64 + t] = a.z + c.z + d4.z + e.z;
        gp[3 * 64 + t] = a.w + c.w + d4.w + e.w;
    }
    __syncthreads();

    // ---- FFN slice prefetch into dead key tile ----
    {
        const float4* g1 = (const float4*)fw1;                   // row = 64 f4
        const float4* g2 = (const float4*)(fw2 + r * 32 * 64);   // 512 f4
        #pragma unroll
        for (int i = 0; i < 2; i++) {
            int idx = t + i * 256;
            int rw = idx >> 3, c = idx & 7;
            CP_ASYNC16(sbase + (FO_FW1 + idx * 4) * 4, g1 + rw * 64 + r * 8 + c);
        }
        #pragma unroll
        for (int i = 0; i < 2; i++) {
            int idx = t + i * 256;
            CP_ASYNC16(sbase + (FO_FW2 + idx * 4) * 4, g2 + idx);
        }
        if (t < 8) {
            CP_ASYNC16(sbase + (FO_FB1 + t * 4) * 4, ((const float4*)(fb1 + r * 32)) + t);
        } else if (t < 24) {
            CP_ASYNC16(sbase + (FO_FB2 + (t - 8) * 4) * 4, ((const float4*)fb2) + (t - 8));
        }
        CP_COMMIT();
    }

    // ---- barrier #2: partials published ----
    __threadfence();
    asm volatile("barrier.cluster.arrive.aligned;" ::: "memory");
    asm volatile("barrier.cluster.wait.aligned;"   ::: "memory");

    // ---- redundant combine per rank ----
    if (t < 32) { m_s[t] = g_pm[b * 32 + t]; l_s[t] = g_pl[b * 32 + t]; }
    __syncthreads();
    if (t < 32) {   // lane = s*4+h over 8 splits
        float m = m_s[t], lv = l_s[t];
        float M = m;
        M = fmaxf(M, __shfl_xor_sync(0xffffffffu, M, 4));
        M = fmaxf(M, __shfl_xor_sync(0xffffffffu, M, 8));
        M = fmaxf(M, __shfl_xor_sync(0xffffffffu, M, 16));
        float f = __expf(m - M);
        f_s[t] = f;
        float L = lv * f;
        L += __shfl_xor_sync(0xffffffffu, L, 4);
        L += __shfl_xor_sync(0xffffffffu, L, 8);
        L += __shfl_xor_sync(0xffffffffu, L, 16);
        if (t < 4) sc_s[t] = sm[OFF_QM] / L;
    }
    __syncthreads();

    float* s_sm   = sm + OFF_ACC;
    float* part_s = sm + OFF_ACC + 256;
    float* res_s  = sm + OFF_KS + FO_RES;
    float* hid_s  = sm + OFF_KS + FO_HID;
    float* fw1s   = sm + OFF_KS + FO_FW1;
    float* fw2s   = sm + OFF_KS + FO_FW2;

    // s_sm[h*64+d] = (sum_s pacc) * qm/L
    {
        int d = t & 63, h = t >> 6;
        float S = 0.f;
        #pragma unroll
        for (int s = 0; s < NRANK; s++)
            S += g_pacc[b * (NRANK * 256) + s * 256 + h * 64 + d] * f_s[s * 4 + h];
        s_sm[h * 64 + d] = S * sc_s[h];
    }
    __syncthreads();

    // res[j] = s_sm[h(j)] @ W_V[:,j] + q0[j]   (W_V L2-broadcast demand loads)
    {
        int j = t & 63, q = t >> 6;
        int h = j >> 4;
        float a = 0.f;
        #pragma unroll
        for (int d = q * 16; d < q * 16 + 16; d++) a += s_sm[h * 64 + d] * W_V[d * 64 + j];
        part_s[t] = a;
    }
    CP_WAIT_GROUP(0);
    __syncthreads();
    if (t < 64) {
        float o = part_s[t] + part_s[64 + t] + part_s[128 + t] + part_s[192 + t];
        res_s[t] = o + q0[t];
    }
    __syncthreads();

    // hidden slice (32 units): thread (m = t&31, jq = t>>5) -> 8 j each
    {
        int m = t & 31, jq = t >> 5;
        float a = 0.f;
        #pragma unroll
        for (int j = jq * 8; j < jq * 8 + 8; j++) a += res_s[j] * fw1s[j * 32 + m];
        part_s[jq * 32 + m] = a;
    }
    __syncthreads();
    if (t < 32) {
        float a = sm[OFF_KS + FO_FB1 + t];
        #pragma unroll
        for (int w = 0; w < 8; w++) a += part_s[w * 32 + t];
        hid_s[t] = (a > 0.f) ? a : 0.2f * a;
    }
    __syncthreads();

    // output partial over this rank's 32 hidden units
    {
        int j = t & 63, mq = t >> 6;
        float a = 0.f;
        #pragma unroll
        for (int m2 = mq * 8; m2 < mq * 8 + 8; m2++) a += hid_s[m2] * fw2s[m2 * 64 + j];
        part_s[t] = a;
    }
    __syncthreads();
    if (t < 64) {
        float v = part_s[t] + part_s[64 + t] + part_s[128 + t] + part_s[192 + t];
        if (r == 0) v += res_s[t] + sm[OFF_KS + FO_FB2 + t];
        atomicAdd(&out[b * 64 + t], v);
    }
}

extern "C" void kernel_launch(void* const* d_in, const int* in_sizes, int n_in,
                              void* d_out, int out_size)
{
    const float* queries = (const float*)d_in[0];
    const float* keys    = (const float*)d_in[1];
    const int*   qmask   = (const int*)d_in[2];
    const int*   kmask   = (const int*)d_in[3];
    const float* W_Q     = (const float*)d_in[4];
    const float* W_K     = (const float*)d_in[5];
    const float* W_V     = (const float*)d_in[6];
    const float* fw1     = (const float*)d_in[7];
    const float* fw2     = (const float*)d_in[8];
    const float* fb1     = (const float*)d_in[9];
    const float* fb2     = (const float*)d_in[10];
    float* out = (float*)d_out;

    cudaFuncSetAttribute(fused_transformer_kernel,
                         cudaFuncAttributeMaxDynamicSharedMemorySize, SM_BYTES);

    fused_transformer_kernel<<<dim3(NRANK, BB), 256, SM_BYTES>>>(
        queries, keys, qmask, kmask, W_Q, W_K, W_V, fw1, fw2, fb1, fb2, out);
}